// round 1
// baseline (speedup 1.0000x reference)
#include <cuda_runtime.h>
#include <cstdint>

#define BHX   32
#define SEQ   2048
#define DIMX  64
#define TOPKX 30

// Scratch fallbacks in case d_out holds only one of the two tuple outputs.
// (Static __device__ arrays are the sanctioned scratch mechanism.)
__device__ float g_attn_scratch[(size_t)BHX * SEQ * SEQ];
__device__ float g_ctx_scratch[(size_t)BHX * SEQ * DIMX];

// ---------------------------------------------------------------------------
// Kernel A: scores[bh][n][m] = sum_d q[bh][n][d] * k[bh][m][d]
// Classic SIMT tiled GEMM, 128x128 tile, K=64 (single pass, no k-loop reload).
// ---------------------------------------------------------------------------
__global__ __launch_bounds__(256) void gemm_scores_kernel(
    const float* __restrict__ q,
    const float* __restrict__ k,
    float* __restrict__ scores)
{
    extern __shared__ float sm[];
    // layout: [kk][row], row-stride padded to 132 floats (mult of 4 for LDS.128 align)
    float* Qs = sm;              // 64 * 132
    float* Ks = sm + 64 * 132;   // 64 * 132

    const int bz      = blockIdx.z;
    const int rowBase = blockIdx.y * 128;
    const int colBase = blockIdx.x * 128;
    const int t       = threadIdx.x;

    // Load tiles with transpose: lane-major over rows -> conflict-free STS.
    {
        const int row = t & 127;
        const int cb  = t >> 7;  // 0 or 1
        const float4* gq = reinterpret_cast<const float4*>(
            q + ((size_t)bz * SEQ + rowBase + row) * DIMX);
        const float4* gk = reinterpret_cast<const float4*>(
            k + ((size_t)bz * SEQ + colBase + row) * DIMX);
#pragma unroll
        for (int i = 0; i < 8; i++) {
            const int c = cb + 2 * i;  // 0..15
            float4 a = gq[c];
            float4 b = gk[c];
            Qs[(4 * c + 0) * 132 + row] = a.x;
            Qs[(4 * c + 1) * 132 + row] = a.y;
            Qs[(4 * c + 2) * 132 + row] = a.z;
            Qs[(4 * c + 3) * 132 + row] = a.w;
            Ks[(4 * c + 0) * 132 + row] = b.x;
            Ks[(4 * c + 1) * 132 + row] = b.y;
            Ks[(4 * c + 2) * 132 + row] = b.z;
            Ks[(4 * c + 3) * 132 + row] = b.w;
        }
    }
    __syncthreads();

    const int tx = t & 15;   // col group
    const int ty = t >> 4;   // row group

    float acc[8][8];
#pragma unroll
    for (int i = 0; i < 8; i++)
#pragma unroll
        for (int j = 0; j < 8; j++) acc[i][j] = 0.0f;

#pragma unroll 8
    for (int kk = 0; kk < 64; kk++) {
        const float4 a0 = *reinterpret_cast<const float4*>(&Qs[kk * 132 + ty * 8]);
        const float4 a1 = *reinterpret_cast<const float4*>(&Qs[kk * 132 + ty * 8 + 4]);
        const float4 b0 = *reinterpret_cast<const float4*>(&Ks[kk * 132 + tx * 8]);
        const float4 b1 = *reinterpret_cast<const float4*>(&Ks[kk * 132 + tx * 8 + 4]);
        const float a[8] = {a0.x, a0.y, a0.z, a0.w, a1.x, a1.y, a1.z, a1.w};
        const float b[8] = {b0.x, b0.y, b0.z, b0.w, b1.x, b1.y, b1.z, b1.w};
#pragma unroll
        for (int i = 0; i < 8; i++)
#pragma unroll
            for (int j = 0; j < 8; j++) acc[i][j] = fmaf(a[i], b[j], acc[i][j]);
    }

#pragma unroll
    for (int i = 0; i < 8; i++) {
        float4* o = reinterpret_cast<float4*>(
            scores + ((size_t)bz * SEQ + rowBase + ty * 8 + i) * SEQ + colBase + tx * 8);
        o[0] = make_float4(acc[i][0], acc[i][1], acc[i][2], acc[i][3]);
        o[1] = make_float4(acc[i][4], acc[i][5], acc[i][6], acc[i][7]);
    }
}

// ---------------------------------------------------------------------------
// Kernel B: per row — exact top-30 selection, masked softmax, rewrite attn row
// (zeros + weights) in place, and compute context = attn @ v.
// One warp per row; 8 rows per 256-thread block.
// ---------------------------------------------------------------------------
__device__ __forceinline__ unsigned f2key(float s) {
    unsigned u = __float_as_uint(s);
    return (u & 0x80000000u) ? ~u : (u | 0x80000000u);
}
__device__ __forceinline__ float key2f(unsigned key) {
    unsigned u = (key & 0x80000000u) ? (key ^ 0x80000000u) : ~key;
    return __uint_as_float(u);
}

__global__ __launch_bounds__(256) void topk_softmax_ctx_kernel(
    float* __restrict__ attn,        // scores in, attn out (in place)
    const float* __restrict__ v,
    float* __restrict__ ctx)
{
    const int wid  = threadIdx.x >> 5;
    const int lane = threadIdx.x & 31;
    const size_t r = (size_t)blockIdx.x * 8 + wid;   // global row 0..65535
    const int bh   = (int)(r >> 11);

    __shared__ int   scols[8][TOPKX];
    __shared__ float sws[8][TOPKX];
    __shared__ int   scnt[8];
    if (lane == 0) scnt[wid] = 0;
    __syncwarp();

    float* rowp = attn + r * SEQ;
    const float4* rp4 = reinterpret_cast<const float4*>(rowp);

    // Cache row as sortable keys: keys[4*i+j] <-> col = i*128 + lane*4 + j
    unsigned keys[64];
#pragma unroll
    for (int i = 0; i < 16; i++) {
        float4 v4 = rp4[i * 32 + lane];
        keys[4 * i + 0] = f2key(v4.x);
        keys[4 * i + 1] = f2key(v4.y);
        keys[4 * i + 2] = f2key(v4.z);
        keys[4 * i + 3] = f2key(v4.w);
    }

    unsigned long long selmask = 0ull;
    unsigned a0, a1, a2, a3;   // per-lane top-4 key cache (descending)
    int p0, p1, p2, p3;        // positions

    auto rebuild = [&]() {
        a0 = a1 = a2 = a3 = 0u;
        p0 = p1 = p2 = p3 = 0;
#pragma unroll
        for (int pos = 0; pos < 64; pos++) {
            if ((selmask >> pos) & 1ull) continue;
            unsigned key = keys[pos];
            if (key > a3) {
                a3 = key; p3 = pos;
                if (a3 > a2) { unsigned tk = a2; a2 = a3; a3 = tk; int tp = p2; p2 = p3; p3 = tp; }
                if (a2 > a1) { unsigned tk = a1; a1 = a2; a2 = tk; int tp = p1; p1 = p2; p2 = tp; }
                if (a1 > a0) { unsigned tk = a0; a0 = a1; a1 = tk; int tp = p0; p0 = p1; p1 = tp; }
            }
        }
    };

    rebuild();
    int p = 0;
    unsigned mkey = 0, tkey = 0;
    for (int it = 0; it < TOPKX; it++) {
        if (p == 4) { rebuild(); p = 0; }
        unsigned head = (p == 0) ? a0 : (p == 1) ? a1 : (p == 2) ? a2 : a3;
        unsigned wmax = __reduce_max_sync(0xffffffffu, head);
        if (it == 0) mkey = wmax;
        tkey = wmax;
        unsigned ball = __ballot_sync(0xffffffffu, head == wmax);
        if (lane == (__ffs(ball) - 1)) {
            int pos = (p == 0) ? p0 : (p == 1) ? p1 : (p == 2) ? p2 : p3;
            selmask |= 1ull << pos;
            p++;
        }
    }
    (void)tkey;

    const float m = key2f(mkey);

    // Z = sum over selected of exp(s - m)
    float z = 0.0f;
#pragma unroll
    for (int pos = 0; pos < 64; pos++) {
        if ((selmask >> pos) & 1ull) z += __expf(key2f(keys[pos]) - m);
    }
#pragma unroll
    for (int off = 16; off > 0; off >>= 1)
        z += __shfl_xor_sync(0xffffffffu, z, off);
    const float invZ = 1.0f / z;

    // Rewrite the row: weights at selected cols, zeros elsewhere; push (col,w).
#pragma unroll
    for (int i = 0; i < 16; i++) {
        float o4[4];
#pragma unroll
        for (int j = 0; j < 4; j++) {
            const int pos = 4 * i + j;
            float val = 0.0f;
            if ((selmask >> pos) & 1ull) {
                float w = __expf(key2f(keys[pos]) - m) * invZ;
                val = w;
                int idx = atomicAdd(&scnt[wid], 1);
                scols[wid][idx] = i * 128 + lane * 4 + j;
                sws[wid][idx]   = w;
            }
            o4[j] = val;
        }
        reinterpret_cast<float4*>(rowp)[i * 32 + lane] =
            make_float4(o4[0], o4[1], o4[2], o4[3]);
    }
    __syncwarp();

    // context[r][:] = sum_j w_j * v[bh][col_j][:]
    float c0 = 0.0f, c1 = 0.0f;
    const float* vb = v + (size_t)bh * SEQ * DIMX;
#pragma unroll 5
    for (int j = 0; j < TOPKX; j++) {
        const float w = sws[wid][j];
        const float* vp = vb + (size_t)scols[wid][j] * DIMX;
        c0 = fmaf(w, vp[lane], c0);
        c1 = fmaf(w, vp[lane + 32], c1);
    }
    ctx[r * DIMX + lane]      = c0;
    ctx[r * DIMX + lane + 32] = c1;
}

// ---------------------------------------------------------------------------
extern "C" void kernel_launch(void* const* d_in, const int* in_sizes, int n_in,
                              void* d_out, int out_size)
{
    const float* q = (const float*)d_in[0];
    const float* k = (const float*)d_in[1];
    const float* v = (const float*)d_in[2];

    const size_t CTX = (size_t)BHX * SEQ * DIMX;       // 4,194,304
    const size_t ATT = (size_t)BHX * SEQ * SEQ;        // 134,217,728

    float* outp = (float*)d_out;
    float* ctx;
    float* attn;
    if ((size_t)out_size >= CTX + ATT) {
        ctx  = outp;            // tuple order: (context, attn)
        attn = outp + CTX;
    } else if ((size_t)out_size >= ATT) {
        attn = outp;
        cudaGetSymbolAddress((void**)&ctx, g_ctx_scratch);
    } else {
        ctx = outp;
        cudaGetSymbolAddress((void**)&attn, g_attn_scratch);
    }

    const int smemA = 2 * 64 * 132 * sizeof(float);    // 67,584 B
    cudaFuncSetAttribute(gemm_scores_kernel,
                         cudaFuncAttributeMaxDynamicSharedMemorySize, smemA);

    dim3 gridA(SEQ / 128, SEQ / 128, BHX);             // 16 x 16 x 32
    gemm_scores_kernel<<<gridA, 256, smemA>>>(q, k, attn);

    dim3 gridB((BHX * SEQ) / 8);                       // 8192 blocks
    topk_softmax_ctx_kernel<<<gridB, 256>>>(attn, v, ctx);
}

// round 2
// speedup vs baseline: 1.6091x; 1.6091x over previous
#include <cuda_runtime.h>
#include <cstdint>

#define BHX   32
#define SEQ   2048
#define DIMX  64
#define TOPKX 30

// Scratch fallbacks in case d_out holds only one of the two tuple outputs.
__device__ float g_attn_scratch[(size_t)BHX * SEQ * SEQ];
__device__ float g_ctx_scratch[(size_t)BHX * SEQ * DIMX];

// ---------------------------------------------------------------------------
// Kernel A: scores[bh][n][m] = sum_d q[bh][n][d] * k[bh][m][d]
// SIMT tiled GEMM, 128x128 tile, K=64. At FFMA roofline.
// ---------------------------------------------------------------------------
__global__ __launch_bounds__(256) void gemm_scores_kernel(
    const float* __restrict__ q,
    const float* __restrict__ k,
    float* __restrict__ scores)
{
    extern __shared__ float sm[];
    float* Qs = sm;              // 64 * 132
    float* Ks = sm + 64 * 132;   // 64 * 132

    const int bz      = blockIdx.z;
    const int rowBase = blockIdx.y * 128;
    const int colBase = blockIdx.x * 128;
    const int t       = threadIdx.x;

    {
        const int row = t & 127;
        const int cb  = t >> 7;
        const float4* gq = reinterpret_cast<const float4*>(
            q + ((size_t)bz * SEQ + rowBase + row) * DIMX);
        const float4* gk = reinterpret_cast<const float4*>(
            k + ((size_t)bz * SEQ + colBase + row) * DIMX);
#pragma unroll
        for (int i = 0; i < 8; i++) {
            const int c = cb + 2 * i;
            float4 a = gq[c];
            float4 b = gk[c];
            Qs[(4 * c + 0) * 132 + row] = a.x;
            Qs[(4 * c + 1) * 132 + row] = a.y;
            Qs[(4 * c + 2) * 132 + row] = a.z;
            Qs[(4 * c + 3) * 132 + row] = a.w;
            Ks[(4 * c + 0) * 132 + row] = b.x;
            Ks[(4 * c + 1) * 132 + row] = b.y;
            Ks[(4 * c + 2) * 132 + row] = b.z;
            Ks[(4 * c + 3) * 132 + row] = b.w;
        }
    }
    __syncthreads();

    const int tx = t & 15;
    const int ty = t >> 4;

    float acc[8][8];
#pragma unroll
    for (int i = 0; i < 8; i++)
#pragma unroll
        for (int j = 0; j < 8; j++) acc[i][j] = 0.0f;

#pragma unroll 8
    for (int kk = 0; kk < 64; kk++) {
        const float4 a0 = *reinterpret_cast<const float4*>(&Qs[kk * 132 + ty * 8]);
        const float4 a1 = *reinterpret_cast<const float4*>(&Qs[kk * 132 + ty * 8 + 4]);
        const float4 b0 = *reinterpret_cast<const float4*>(&Ks[kk * 132 + tx * 8]);
        const float4 b1 = *reinterpret_cast<const float4*>(&Ks[kk * 132 + tx * 8 + 4]);
        const float a[8] = {a0.x, a0.y, a0.z, a0.w, a1.x, a1.y, a1.z, a1.w};
        const float b[8] = {b0.x, b0.y, b0.z, b0.w, b1.x, b1.y, b1.z, b1.w};
#pragma unroll
        for (int i = 0; i < 8; i++)
#pragma unroll
            for (int j = 0; j < 8; j++) acc[i][j] = fmaf(a[i], b[j], acc[i][j]);
    }

#pragma unroll
    for (int i = 0; i < 8; i++) {
        float4* o = reinterpret_cast<float4*>(
            scores + ((size_t)bz * SEQ + rowBase + ty * 8 + i) * SEQ + colBase + tx * 8);
        o[0] = make_float4(acc[i][0], acc[i][1], acc[i][2], acc[i][3]);
        o[1] = make_float4(acc[i][4], acc[i][5], acc[i][6], acc[i][7]);
    }
}

// ---------------------------------------------------------------------------
// Kernel B: per row — exact top-30 via per-lane top-4 caches + REDUX.MAX,
// masked softmax, zero-fill + scatter attn row, context gather.
// One warp per row; 8 rows per 256-thread block. No register row cache.
// ---------------------------------------------------------------------------
__device__ __forceinline__ unsigned f2key(float s) {
    unsigned u = __float_as_uint(s);
    return (u & 0x80000000u) ? ~u : (u | 0x80000000u);
}
__device__ __forceinline__ float key2f(unsigned key) {
    unsigned u = (key & 0x80000000u) ? (key ^ 0x80000000u) : ~key;
    return __uint_as_float(u);
}

__global__ __launch_bounds__(256) void topk_softmax_ctx_kernel(
    float* __restrict__ attn,        // scores in, attn out (in place)
    const float* __restrict__ v,
    float* __restrict__ ctx)
{
    const int wid  = threadIdx.x >> 5;
    const int lane = threadIdx.x & 31;
    const size_t r = (size_t)blockIdx.x * 8 + wid;
    const int bh   = (int)(r >> 11);

    __shared__ int   scols[8][32];
    __shared__ float sws[8][32];

    float* rowp = attn + r * SEQ;
    const float4* rp4 = reinterpret_cast<const float4*>(rowp);

    // Per-lane sorted top-4 (descending): keys a0..a3, packed positions p0..p3.
    // pos = 4*i + j  <->  col = i*128 + lane*4 + j
    unsigned a0 = 0, a1 = 0, a2 = 0, a3 = 0;
    int p0 = 0, p1 = 0, p2 = 0, p3 = 0;

#pragma unroll
    for (int i = 0; i < 16; i++) {
        float4 v4 = rp4[i * 32 + lane];
        float vv[4] = {v4.x, v4.y, v4.z, v4.w};
#pragma unroll
        for (int j = 0; j < 4; j++) {
            unsigned key = f2key(vv[j]);
            int pos = 4 * i + j;
            if (key > a3) {
                if (key > a2) {
                    a3 = a2; p3 = p2;
                    if (key > a1) {
                        a2 = a1; p2 = p1;
                        if (key > a0) { a1 = a0; p1 = p0; a0 = key; p0 = pos; }
                        else          { a1 = key; p1 = pos; }
                    } else { a2 = key; p2 = pos; }
                } else { a3 = key; p3 = pos; }
            }
        }
    }

    unsigned long long selmask = 0ull;  // per-lane selected positions
    int nvalid = 4;

    for (int it = 0; it < TOPKX; it++) {
        unsigned wmax = __reduce_max_sync(0xffffffffu, a0);
        unsigned ball = __ballot_sync(0xffffffffu, a0 == wmax);
        if (lane == (__ffs(ball) - 1)) {
            // record selection
            int col = (p0 >> 2) * 128 + lane * 4 + (p0 & 3);
            scols[wid][it] = col;
            sws[wid][it]   = key2f(wmax);   // raw value for now
            selmask |= 1ull << p0;
            // pop head
            a0 = a1; p0 = p1; a1 = a2; p1 = p2; a2 = a3; p2 = p3; a3 = 0;
            nvalid--;
            if (nvalid == 0) {
                // rare rebuild: re-read this lane's 64 columns from global
#pragma unroll
                for (int i = 0; i < 16; i++) {
                    float4 v4 = rp4[i * 32 + lane];
                    float vv[4] = {v4.x, v4.y, v4.z, v4.w};
#pragma unroll
                    for (int j = 0; j < 4; j++) {
                        int pos = 4 * i + j;
                        if ((selmask >> pos) & 1ull) continue;
                        unsigned key = f2key(vv[j]);
                        if (key > a3) {
                            if (key > a2) {
                                a3 = a2; p3 = p2;
                                if (key > a1) {
                                    a2 = a1; p2 = p1;
                                    if (key > a0) { a1 = a0; p1 = p0; a0 = key; p0 = pos; }
                                    else          { a1 = key; p1 = pos; }
                                } else { a2 = key; p2 = pos; }
                            } else { a3 = key; p3 = pos; }
                        }
                    }
                }
                nvalid = 4;   // >=34 unselected remain, always refills
            }
        }
    }
    __syncwarp();

    // Softmax over the 30 selected values (values sit in sws in desc order).
    const float m = sws[wid][0];
    float e = 0.0f;
    if (lane < TOPKX) {
        e = __expf(sws[wid][lane] - m);
    }
    float z = e;
#pragma unroll
    for (int off = 16; off > 0; off >>= 1)
        z += __shfl_xor_sync(0xffffffffu, z, off);
    const float invZ = 1.0f / z;
    __syncwarp();
    if (lane < TOPKX) sws[wid][lane] = e * invZ;
    __syncwarp();

    // Zero the row, then scatter the 30 weights.
    const float4 z4 = make_float4(0.f, 0.f, 0.f, 0.f);
#pragma unroll
    for (int i = 0; i < 16; i++)
        reinterpret_cast<float4*>(rowp)[i * 32 + lane] = z4;
    __syncwarp();
    if (lane < TOPKX)
        rowp[scols[wid][lane]] = sws[wid][lane];

    // context[r][:] = sum_j w_j * v[bh][col_j][:]
    float c0 = 0.0f, c1 = 0.0f;
    const float* vb = v + (size_t)bh * SEQ * DIMX;
#pragma unroll 5
    for (int j = 0; j < TOPKX; j++) {
        const float w  = sws[wid][j];
        const float* vp = vb + (size_t)scols[wid][j] * DIMX;
        c0 = fmaf(w, vp[lane], c0);
        c1 = fmaf(w, vp[lane + 32], c1);
    }
    ctx[r * DIMX + lane]      = c0;
    ctx[r * DIMX + lane + 32] = c1;
}

// ---------------------------------------------------------------------------
extern "C" void kernel_launch(void* const* d_in, const int* in_sizes, int n_in,
                              void* d_out, int out_size)
{
    const float* q = (const float*)d_in[0];
    const float* k = (const float*)d_in[1];
    const float* v = (const float*)d_in[2];

    const size_t CTX = (size_t)BHX * SEQ * DIMX;
    const size_t ATT = (size_t)BHX * SEQ * SEQ;

    float* outp = (float*)d_out;
    float* ctx;
    float* attn;
    if ((size_t)out_size >= CTX + ATT) {
        ctx  = outp;            // tuple order: (context, attn)
        attn = outp + CTX;
    } else if ((size_t)out_size >= ATT) {
        attn = outp;
        cudaGetSymbolAddress((void**)&ctx, g_ctx_scratch);
    } else {
        ctx = outp;
        cudaGetSymbolAddress((void**)&attn, g_attn_scratch);
    }

    const int smemA = 2 * 64 * 132 * sizeof(float);
    cudaFuncSetAttribute(gemm_scores_kernel,
                         cudaFuncAttributeMaxDynamicSharedMemorySize, smemA);

    dim3 gridA(SEQ / 128, SEQ / 128, BHX);
    gemm_scores_kernel<<<gridA, 256, smemA>>>(q, k, attn);

    dim3 gridB((BHX * SEQ) / 8);
    topk_softmax_ctx_kernel<<<gridB, 256>>>(attn, v, ctx);
}

// round 4
// speedup vs baseline: 2.3283x; 1.4469x over previous
#include <cuda_runtime.h>
#include <cuda_fp16.h>
#include <cstdint>

#define BHX   32
#define SEQ   2048
#define DIMX  64
#define TOPKX 30

// Scratch fallbacks in case d_out holds only one of the two tuple outputs.
__device__ float g_attn_scratch[(size_t)BHX * SEQ * SEQ];
__device__ float g_ctx_scratch[(size_t)BHX * SEQ * DIMX];

// ===========================================================================
// Kernel A: scores = q @ k^T via fp16x3 mma.sync (Markidis split).
// CTA tile 128x128, K=64 resident. 8 warps (2x4), warp tile 64x32.
// ===========================================================================
__device__ __forceinline__ uint32_t smem_u32(const void* p) {
    uint32_t a;
    asm("{ .reg .u64 t; cvta.to.shared.u64 t, %1; cvt.u32.u64 %0, t; }"
        : "=r"(a) : "l"(p));
    return a;
}

#define LDSM_X4(r0, r1, r2, r3, addr)                                        \
    asm volatile("ldmatrix.sync.aligned.m8n8.x4.shared.b16 {%0,%1,%2,%3}, [%4];" \
                 : "=r"(r0), "=r"(r1), "=r"(r2), "=r"(r3) : "r"(addr))

#define MMA_16816(d, a0, a1, a2, a3, b0, b1)                                 \
    asm volatile("mma.sync.aligned.m16n8k16.row.col.f32.f16.f16.f32 "        \
                 "{%0,%1,%2,%3}, {%4,%5,%6,%7}, {%8,%9}, {%0,%1,%2,%3};"     \
                 : "+f"((d)[0]), "+f"((d)[1]), "+f"((d)[2]), "+f"((d)[3])    \
                 : "r"(a0), "r"(a1), "r"(a2), "r"(a3), "r"(b0), "r"(b1))

// smem tile layout: 128 rows x 64 halves (128B/row). 16B chunk c (0..7) at
// byte = row*128 + ((c ^ (row&7)) << 4)  -> conflict-free ldmatrix.
#define TILE_B  16384
#define A_HI_O  0
#define A_LO_O  16384
#define B_HI_O  32768
#define B_LO_O  49152
#define SMEM_A_DYN 65536

__global__ __launch_bounds__(256, 2) void gemm_hmma_kernel(
    const float* __restrict__ q,
    const float* __restrict__ k,
    float* __restrict__ scores)
{
    extern __shared__ char sm[];
    const uint32_t smb = smem_u32(sm);

    const int t    = threadIdx.x;
    const int wid  = t >> 5;
    const int lane = t & 31;

    const int colBase = blockIdx.x * 128;   // k rows (score cols)
    const int rowBase = blockIdx.y * 128;   // q rows
    const int bh      = blockIdx.z;

    // ---- Load + split q,k tiles (each 128 x 64 fp32 -> hi/lo fp16) ----
    {
        const float4* gq = reinterpret_cast<const float4*>(
            q + ((size_t)bh * SEQ + rowBase) * DIMX);
        const float4* gk = reinterpret_cast<const float4*>(
            k + ((size_t)bh * SEQ + colBase) * DIMX);
#pragma unroll
        for (int it = 0; it < 8; it++) {
            const int fi  = t + it * 256;      // 0..2047
            const int row = fi >> 4;
            const int c4  = fi & 15;           // float4 index within row
            const uint32_t off = (uint32_t)(row * 128)
                + ((((c4 >> 1) ^ (row & 7)) << 4)) + ((c4 & 1) << 3);

            float4 a = gq[row * 16 + c4];
            {
                __half hx = __float2half_rn(a.x), hy = __float2half_rn(a.y);
                __half hz = __float2half_rn(a.z), hw = __float2half_rn(a.w);
                __half lx = __float2half_rn(a.x - __half2float(hx));
                __half ly = __float2half_rn(a.y - __half2float(hy));
                __half lz = __float2half_rn(a.z - __half2float(hz));
                __half lw = __float2half_rn(a.w - __half2float(hw));
                uint2 hv = make_uint2(
                    (uint32_t)__half_as_ushort(hx) | ((uint32_t)__half_as_ushort(hy) << 16),
                    (uint32_t)__half_as_ushort(hz) | ((uint32_t)__half_as_ushort(hw) << 16));
                uint2 lv = make_uint2(
                    (uint32_t)__half_as_ushort(lx) | ((uint32_t)__half_as_ushort(ly) << 16),
                    (uint32_t)__half_as_ushort(lz) | ((uint32_t)__half_as_ushort(lw) << 16));
                *reinterpret_cast<uint2*>(sm + A_HI_O + off) = hv;
                *reinterpret_cast<uint2*>(sm + A_LO_O + off) = lv;
            }
            float4 b = gk[row * 16 + c4];
            {
                __half hx = __float2half_rn(b.x), hy = __float2half_rn(b.y);
                __half hz = __float2half_rn(b.z), hw = __float2half_rn(b.w);
                __half lx = __float2half_rn(b.x - __half2float(hx));
                __half ly = __float2half_rn(b.y - __half2float(hy));
                __half lz = __float2half_rn(b.z - __half2float(hz));
                __half lw = __float2half_rn(b.w - __half2float(hw));
                uint2 hv = make_uint2(
                    (uint32_t)__half_as_ushort(hx) | ((uint32_t)__half_as_ushort(hy) << 16),
                    (uint32_t)__half_as_ushort(hz) | ((uint32_t)__half_as_ushort(hw) << 16));
                uint2 lv = make_uint2(
                    (uint32_t)__half_as_ushort(lx) | ((uint32_t)__half_as_ushort(ly) << 16),
                    (uint32_t)__half_as_ushort(lz) | ((uint32_t)__half_as_ushort(lw) << 16));
                *reinterpret_cast<uint2*>(sm + B_HI_O + off) = hv;
                *reinterpret_cast<uint2*>(sm + B_LO_O + off) = lv;
            }
        }
    }
    __syncthreads();

    // ---- Warp tiles: 2 (M) x 4 (N) warps; warp tile 64x32 ----
    const int wm = wid >> 2;        // 0..1
    const int wn = wid & 3;         // 0..3

    float acc[4][4][4];
#pragma unroll
    for (int mi = 0; mi < 4; mi++)
#pragma unroll
        for (int ni = 0; ni < 4; ni++)
#pragma unroll
            for (int f = 0; f < 4; f++) acc[mi][ni][f] = 0.0f;

    // Precompute per-lane ldmatrix row bytes.
    // A (per mi): row = wm*64 + mi*16 + (lane&15); chunk = kk*2 + (lane>>4)
    uint32_t aRowByte[4];
    uint32_t aR7[4];
#pragma unroll
    for (int mi = 0; mi < 4; mi++) {
        const int row = wm * 64 + mi * 16 + (lane & 15);
        aRowByte[mi] = (uint32_t)(row * 128);
        aR7[mi] = (uint32_t)(row & 7);
    }
    const uint32_t aHiSel = (uint32_t)(lane >> 4);   // 0/1 -> k-half

    // B (per ntp in {0,1} covering n-tiles 2*ntp, 2*ntp+1):
    // row = wn*32 + ntp*16 + (lane&7) + (lane>>4)*8 ; chunk = kk*2 + ((lane>>3)&1)
    uint32_t bRowByte[2];
    uint32_t bR7[2];
#pragma unroll
    for (int ntp = 0; ntp < 2; ntp++) {
        const int row = wn * 32 + ntp * 16 + (lane & 7) + ((lane >> 4) << 3);
        bRowByte[ntp] = (uint32_t)(row * 128);
        bR7[ntp] = (uint32_t)(row & 7);
    }
    const uint32_t bHiSel = (uint32_t)((lane >> 3) & 1);

    const uint32_t aBase[3] = {smb + A_HI_O, smb + A_HI_O, smb + A_LO_O};
    const uint32_t bBase[3] = {smb + B_HI_O, smb + B_LO_O, smb + B_HI_O};

#pragma unroll
    for (int s = 0; s < 3; s++) {
        const uint32_t ab = aBase[s];
        const uint32_t bb = bBase[s];
#pragma unroll
        for (int kk = 0; kk < 4; kk++) {
            uint32_t a[4][4];
#pragma unroll
            for (int mi = 0; mi < 4; mi++) {
                const uint32_t chunk = (uint32_t)(kk * 2) + aHiSel;
                const uint32_t addr = ab + aRowByte[mi] + (((chunk ^ aR7[mi]) << 4));
                LDSM_X4(a[mi][0], a[mi][1], a[mi][2], a[mi][3], addr);
            }
            uint32_t b[2][4];
#pragma unroll
            for (int ntp = 0; ntp < 2; ntp++) {
                const uint32_t chunk = (uint32_t)(kk * 2) + bHiSel;
                const uint32_t addr = bb + bRowByte[ntp] + (((chunk ^ bR7[ntp]) << 4));
                LDSM_X4(b[ntp][0], b[ntp][1], b[ntp][2], b[ntp][3], addr);
            }
#pragma unroll
            for (int mi = 0; mi < 4; mi++) {
#pragma unroll
                for (int ni = 0; ni < 4; ni++) {
                    const uint32_t b0 = b[ni >> 1][(ni & 1) * 2 + 0];
                    const uint32_t b1 = b[ni >> 1][(ni & 1) * 2 + 1];
                    MMA_16816(acc[mi][ni], a[mi][0], a[mi][1], a[mi][2], a[mi][3], b0, b1);
                }
            }
        }
    }

    // ---- Epilogue: registers -> global (float2 stores, full 32B sectors) ----
    {
        const int r0 = lane >> 2;
        const int c0 = (lane & 3) * 2;
        float* gout = scores + ((size_t)bh * SEQ + rowBase + wm * 64) * SEQ
                      + colBase + wn * 32;
#pragma unroll
        for (int mi = 0; mi < 4; mi++) {
#pragma unroll
            for (int ni = 0; ni < 4; ni++) {
                float* p0 = gout + (size_t)(mi * 16 + r0) * SEQ + ni * 8 + c0;
                float* p1 = p0 + 8 * SEQ;
                *reinterpret_cast<float2*>(p0) = make_float2(acc[mi][ni][0], acc[mi][ni][1]);
                *reinterpret_cast<float2*>(p1) = make_float2(acc[mi][ni][2], acc[mi][ni][3]);
            }
        }
    }
}

// ===========================================================================
// Kernel B: per-row exact top-30 + masked softmax + scatter + context.
// (unchanged from R2 — 319us)
// ===========================================================================
__device__ __forceinline__ unsigned f2key(float s) {
    unsigned u = __float_as_uint(s);
    return (u & 0x80000000u) ? ~u : (u | 0x80000000u);
}
__device__ __forceinline__ float key2f(unsigned key) {
    unsigned u = (key & 0x80000000u) ? (key ^ 0x80000000u) : ~key;
    return __uint_as_float(u);
}

__global__ __launch_bounds__(256) void topk_softmax_ctx_kernel(
    float* __restrict__ attn,
    const float* __restrict__ v,
    float* __restrict__ ctx)
{
    const int wid  = threadIdx.x >> 5;
    const int lane = threadIdx.x & 31;
    const size_t r = (size_t)blockIdx.x * 8 + wid;
    const int bh   = (int)(r >> 11);

    __shared__ int   scols[8][32];
    __shared__ float sws[8][32];

    float* rowp = attn + r * SEQ;
    const float4* rp4 = reinterpret_cast<const float4*>(rowp);

    unsigned a0 = 0, a1 = 0, a2 = 0, a3 = 0;
    int p0 = 0, p1 = 0, p2 = 0, p3 = 0;

#pragma unroll
    for (int i = 0; i < 16; i++) {
        float4 v4 = rp4[i * 32 + lane];
        float vv[4] = {v4.x, v4.y, v4.z, v4.w};
#pragma unroll
        for (int j = 0; j < 4; j++) {
            unsigned key = f2key(vv[j]);
            int pos = 4 * i + j;
            if (key > a3) {
                if (key > a2) {
                    a3 = a2; p3 = p2;
                    if (key > a1) {
                        a2 = a1; p2 = p1;
                        if (key > a0) { a1 = a0; p1 = p0; a0 = key; p0 = pos; }
                        else          { a1 = key; p1 = pos; }
                    } else { a2 = key; p2 = pos; }
                } else { a3 = key; p3 = pos; }
            }
        }
    }

    unsigned long long selmask = 0ull;
    int nvalid = 4;

    for (int it = 0; it < TOPKX; it++) {
        unsigned wmax = __reduce_max_sync(0xffffffffu, a0);
        unsigned ball = __ballot_sync(0xffffffffu, a0 == wmax);
        if (lane == (__ffs(ball) - 1)) {
            int col = (p0 >> 2) * 128 + lane * 4 + (p0 & 3);
            scols[wid][it] = col;
            sws[wid][it]   = key2f(wmax);
            selmask |= 1ull << p0;
            a0 = a1; p0 = p1; a1 = a2; p1 = p2; a2 = a3; p2 = p3; a3 = 0;
            nvalid--;
            if (nvalid == 0) {
#pragma unroll
                for (int i = 0; i < 16; i++) {
                    float4 v4 = rp4[i * 32 + lane];
                    float vv[4] = {v4.x, v4.y, v4.z, v4.w};
#pragma unroll
                    for (int j = 0; j < 4; j++) {
                        int pos = 4 * i + j;
                        if ((selmask >> pos) & 1ull) continue;
                        unsigned key = f2key(vv[j]);
                        if (key > a3) {
                            if (key > a2) {
                                a3 = a2; p3 = p2;
                                if (key > a1) {
                                    a2 = a1; p2 = p1;
                                    if (key > a0) { a1 = a0; p1 = p0; a0 = key; p0 = pos; }
                                    else          { a1 = key; p1 = pos; }
                                } else { a2 = key; p2 = pos; }
                            } else { a3 = key; p3 = pos; }
                        }
                    }
                }
                nvalid = 4;
            }
        }
    }
    __syncwarp();

    const float m = sws[wid][0];
    float e = 0.0f;
    if (lane < TOPKX) e = __expf(sws[wid][lane] - m);
    float z = e;
#pragma unroll
    for (int off = 16; off > 0; off >>= 1)
        z += __shfl_xor_sync(0xffffffffu, z, off);
    const float invZ = 1.0f / z;
    __syncwarp();
    if (lane < TOPKX) sws[wid][lane] = e * invZ;
    __syncwarp();

    const float4 z4 = make_float4(0.f, 0.f, 0.f, 0.f);
#pragma unroll
    for (int i = 0; i < 16; i++)
        reinterpret_cast<float4*>(rowp)[i * 32 + lane] = z4;
    __syncwarp();
    if (lane < TOPKX)
        rowp[scols[wid][lane]] = sws[wid][lane];

    float c0 = 0.0f, c1 = 0.0f;
    const float* vb = v + (size_t)bh * SEQ * DIMX;
#pragma unroll 5
    for (int j = 0; j < TOPKX; j++) {
        const float w  = sws[wid][j];
        const float* vp = vb + (size_t)scols[wid][j] * DIMX;
        c0 = fmaf(w, vp[lane], c0);
        c1 = fmaf(w, vp[lane + 32], c1);
    }
    ctx[r * DIMX + lane]      = c0;
    ctx[r * DIMX + lane + 32] = c1;
}

// ---------------------------------------------------------------------------
extern "C" void kernel_launch(void* const* d_in, const int* in_sizes, int n_in,
                              void* d_out, int out_size)
{
    const float* q = (const float*)d_in[0];
    const float* k = (const float*)d_in[1];
    const float* v = (const float*)d_in[2];

    const size_t CTX = (size_t)BHX * SEQ * DIMX;
    const size_t ATT = (size_t)BHX * SEQ * SEQ;

    float* outp = (float*)d_out;
    float* ctx;
    float* attn;
    if ((size_t)out_size >= CTX + ATT) {
        ctx  = outp;
        attn = outp + CTX;
    } else if ((size_t)out_size >= ATT) {
        attn = outp;
        cudaGetSymbolAddress((void**)&ctx, g_ctx_scratch);
    } else {
        ctx = outp;
        cudaGetSymbolAddress((void**)&attn, g_attn_scratch);
    }

    cudaFuncSetAttribute(gemm_hmma_kernel,
                         cudaFuncAttributeMaxDynamicSharedMemorySize, SMEM_A_DYN);

    dim3 gridA(SEQ / 128, SEQ / 128, BHX);   // 16 x 16 x 32
    gemm_hmma_kernel<<<gridA, 256, SMEM_A_DYN>>>(q, k, attn);

    dim3 gridB((BHX * SEQ) / 8);
    topk_softmax_ctx_kernel<<<gridB, 256>>>(attn, v, ctx);
}